// round 14
// baseline (speedup 1.0000x reference)
#include <cuda_runtime.h>
#include <cuda_bf16.h>
#include <cstdint>

// Problem constants
#define BT    65536   // B*T
#define CDIM  128
#define HDIM  64
#define TSEQ  512
#define SCALE 0.088388347648318447f   // 1/sqrt(128)

// q/k scratch bf16 hi/lo in [B][T][H]; v scratch bf16 hi/lo in [B][H][T]
__device__ __nv_bfloat16 g_qhi[BT * HDIM];
__device__ __nv_bfloat16 g_qlo[BT * HDIM];
__device__ __nv_bfloat16 g_khi[BT * HDIM];
__device__ __nv_bfloat16 g_klo[BT * HDIM];
__device__ __nv_bfloat16 g_vhi[BT * HDIM];
__device__ __nv_bfloat16 g_vlo[BT * HDIM];

// pre-split weight images (k0 output), row-major [n][k], k stride 128 bf16
__device__ __nv_bfloat16 g_wgh[128 * 128];
__device__ __nv_bfloat16 g_wgl[128 * 128];
__device__ __nv_bfloat16 g_wqkvh[192 * 128];
__device__ __nv_bfloat16 g_wqkvl[192 * 128];

// ---------------------------------------------------------------------------
// helpers
// ---------------------------------------------------------------------------
__device__ __forceinline__ uint32_t smem_u32(const void* p) {
    uint32_t a;
    asm("{ .reg .u64 t; cvta.to.shared.u64 t, %1; cvt.u32.u64 %0, t; }"
        : "=r"(a) : "l"(p));
    return a;
}
__device__ __forceinline__ uint32_t pack_bf16(float lo, float hi) {
    uint32_t r;
    asm("cvt.rn.bf16x2.f32 %0, %1, %2;" : "=r"(r) : "f"(hi), "f"(lo));
    return r;
}
__device__ __forceinline__ float bf16_residual(float v) {
    return v - __bfloat162float(__float2bfloat16(v));
}
__device__ __forceinline__ void split_pack(float v0, float v1,
                                           uint32_t& hi, uint32_t& lo) {
    __nv_bfloat16 h0 = __float2bfloat16(v0);
    __nv_bfloat16 h1 = __float2bfloat16(v1);
    __nv_bfloat162 hh; hh.x = h0; hh.y = h1;
    hi = *reinterpret_cast<uint32_t*>(&hh);
    lo = pack_bf16(v0 - __bfloat162float(h0), v1 - __bfloat162float(h1));
}
__device__ __forceinline__ void mma_bf16(float* d, const uint32_t* a,
                                         const uint32_t* b) {
    asm volatile(
        "mma.sync.aligned.m16n8k16.row.col.f32.bf16.bf16.f32 "
        "{%0,%1,%2,%3}, {%4,%5,%6,%7}, {%8,%9}, {%0,%1,%2,%3};"
        : "+f"(d[0]), "+f"(d[1]), "+f"(d[2]), "+f"(d[3])
        : "r"(a[0]), "r"(a[1]), "r"(a[2]), "r"(a[3]), "r"(b[0]), "r"(b[1]));
}
__device__ __forceinline__ void cp_async16(uint32_t smem_dst, const void* gsrc) {
    asm volatile("cp.async.cg.shared.global [%0], [%1], 16;"
                 :: "r"(smem_dst), "l"(gsrc) : "memory");
}
#define CP_COMMIT() asm volatile("cp.async.commit_group;" ::: "memory")
#define CP_WAIT0()  asm volatile("cp.async.wait_group 0;" ::: "memory")
#define CP_WAIT1()  asm volatile("cp.async.wait_group 1;" ::: "memory")

// ---------------------------------------------------------------------------
// Kernel 0: one-time weight split into bf16 hi/lo global images.
// ---------------------------------------------------------------------------
__global__ __launch_bounds__(256, 4)
void head_k0_split(const float* __restrict__ Wg,
                   const float* __restrict__ Wk,
                   const float* __restrict__ Wq,
                   const float* __restrict__ Wv)
{
    int i = blockIdx.x * 256 + threadIdx.x;
    if (i < 128 * 128) {
        int d = i >> 7, c = i & 127;
        float v = Wg[c * 128 + d];
        __nv_bfloat16 h = __float2bfloat16(v);
        g_wgh[i] = h;
        g_wgl[i] = __float2bfloat16(v - __bfloat162float(h));
    } else if (i < 128 * 128 + 192 * 128) {
        int j = i - 128 * 128;
        int e = j >> 7, c = j & 127;
        float v;
        if (e < 64)       v = Wq[c * 64 + e];
        else if (e < 128) v = Wk[c * 64 + (e - 64)];
        else              v = Wv[c * 64 + (e - 128)];
        __nv_bfloat16 h = __float2bfloat16(v);
        g_wqkvh[j] = h;
        g_wqkvl[j] = __float2bfloat16(v - __bfloat162float(h));
    }
}

// ---------------------------------------------------------------------------
// Kernel 1: gate GEMM + sigmoid-gate + QKV GEMM (bf16x3 HMMA). (R13 version)
// 64-token CTAs, 256 threads = 8 warps = 4 row-groups(16 rows) x 2 N-halves.
// Weights stream as five 64-row chunks through double-buffered B0/B1.
// ---------------------------------------------------------------------------
#define K1_SMEM 104960

__device__ __forceinline__ void gemm_chunk(const uint32_t* AHw, const uint32_t* ALw,
                                           const uint32_t* BHw, const uint32_t* BLw,
                                           int wbase, int g, int qq, int nh,
                                           float acc[4][4]) {
    #pragma unroll
    for (int kk = 0; kk < 8; ++kk) {
        const int kw = kk * 8 + qq;
        const int r0 = wbase + g;
        uint32_t ah[4], al[4];
        ah[0] = AHw[r0 * 68 + kw];       ah[1] = AHw[(r0 + 8) * 68 + kw];
        ah[2] = AHw[r0 * 68 + kw + 4];   ah[3] = AHw[(r0 + 8) * 68 + kw + 4];
        al[0] = ALw[r0 * 68 + kw];       al[1] = ALw[(r0 + 8) * 68 + kw];
        al[2] = ALw[r0 * 68 + kw + 4];   al[3] = ALw[(r0 + 8) * 68 + kw + 4];
        #pragma unroll
        for (int j = 0; j < 4; ++j) {
            const int n = nh * 32 + j * 8 + g;
            uint32_t bh[2] = { BHw[n * 68 + kw], BHw[n * 68 + kw + 4] };
            uint32_t bl[2] = { BLw[n * 68 + kw], BLw[n * 68 + kw + 4] };
            mma_bf16(acc[j], ah, bh);
            mma_bf16(acc[j], ah, bl);
            mma_bf16(acc[j], al, bh);
        }
    }
}

__global__ __launch_bounds__(256, 2)
void head_k1_gate_qkv(const float* __restrict__ x,
                      const float* __restrict__ bg)
{
    extern __shared__ char smc[];
    const uint32_t sbase = smem_u32(smc);
    __nv_bfloat16* AH = reinterpret_cast<__nv_bfloat16*>(smc);
    __nv_bfloat16* AL = reinterpret_cast<__nv_bfloat16*>(smc + 17408);
    float*         bgs = reinterpret_cast<float*>(smc + 104448);
    float*         vT  = reinterpret_cast<float*>(smc);          // overlay

    uint32_t* AHw = reinterpret_cast<uint32_t*>(AH);
    uint32_t* ALw = reinterpret_cast<uint32_t*>(AL);
    const uint32_t* B0H = reinterpret_cast<const uint32_t*>(smc + 34816);
    const uint32_t* B0L = reinterpret_cast<const uint32_t*>(smc + 52224);
    const uint32_t* B1H = reinterpret_cast<const uint32_t*>(smc + 69632);
    const uint32_t* B1L = reinterpret_cast<const uint32_t*>(smc + 87040);

    const int tid   = threadIdx.x;
    const int wid   = tid >> 5;
    const int lane  = tid & 31;
    const int g     = lane >> 2;
    const int qq    = lane & 3;
    const int q2    = qq * 2;
    const int rg    = wid >> 1;         // row group 0..3
    const int nh    = wid & 1;          // N half within a chunk
    const int wbase = rg * 16;
    const int tok0  = blockIdx.x * 64;
    const int bb    = tok0 >> 9;
    const int t0    = tok0 & 511;

    auto issue_chunk = [&](uint32_t dstH, uint32_t dstL,
                           const char* srcH, const char* srcL) {
        for (int i = tid; i < 1024; i += 256) {
            int row = i >> 4, ch = i & 15;
            uint32_t dof = (uint32_t)(row * 272 + ch * 16);
            cp_async16(sbase + dstH + dof, srcH + row * 256 + ch * 16);
            cp_async16(sbase + dstL + dof, srcL + row * 256 + ch * 16);
        }
        CP_COMMIT();
    };

    issue_chunk(34816, 52224, (const char*)g_wgh, (const char*)g_wgl);
    issue_chunk(69632, 87040, (const char*)g_wgh + 64 * 256,
                              (const char*)g_wgl + 64 * 256);

    for (int i = tid; i < 2048; i += 256) {
        int t = i >> 5, c4 = (i & 31) * 4;
        float4 xv = *reinterpret_cast<const float4*>(
                        x + (size_t)(tok0 + t) * CDIM + c4);
        uint32_t h0, l0w, h1, l1w;
        split_pack(xv.x, xv.y, h0, l0w);
        split_pack(xv.z, xv.w, h1, l1w);
        int widx = t * 68 + (c4 >> 1);
        AHw[widx] = h0; AHw[widx + 1] = h1;
        ALw[widx] = l0w; ALw[widx + 1] = l1w;
    }
    if (tid < 128) bgs[tid] = bg[tid];

    float gA[4][4], gB[4][4];
    #pragma unroll
    for (int j = 0; j < 4; j++)
        #pragma unroll
        for (int t = 0; t < 4; t++) { gA[j][t] = 0.f; gB[j][t] = 0.f; }

    // chunk0: gate cols 0..63 (B0)
    CP_WAIT1();
    __syncthreads();
    gemm_chunk(AHw, ALw, B0H, B0L, wbase, g, qq, nh, gA);
    __syncthreads();
    issue_chunk(34816, 52224, (const char*)g_wqkvh, (const char*)g_wqkvl);

    // chunk1: gate cols 64..127 (B1)
    CP_WAIT1();
    __syncthreads();
    gemm_chunk(AHw, ALw, B1H, B1L, wbase, g, qq, nh, gB);

    // gate epilogue
    #pragma unroll
    for (int ck = 0; ck < 2; ++ck) {
        float (*acc)[4] = ck ? gB : gA;
        #pragma unroll
        for (int j = 0; j < 4; ++j) {
            const int col = ck * 64 + nh * 32 + j * 8 + q2;
            #pragma unroll
            for (int hf = 0; hf < 2; ++hf) {
                const int r = wbase + g + hf * 8;
                __nv_bfloat162 hw = *reinterpret_cast<__nv_bfloat162*>(&AH[r * 136 + col]);
                __nv_bfloat162 lw = *reinterpret_cast<__nv_bfloat162*>(&AL[r * 136 + col]);
                float x0 = __bfloat162float(hw.x) + __bfloat162float(lw.x);
                float x1 = __bfloat162float(hw.y) + __bfloat162float(lw.y);
                float c0 = acc[j][hf * 2 + 0], c1 = acc[j][hf * 2 + 1];
                float g0 = 1.f / (1.f + __expf(-(c0 + bgs[col])));
                float g1 = 1.f / (1.f + __expf(-(c1 + bgs[col + 1])));
                uint32_t hiw, low;
                split_pack(x0 * g0, x1 * g1, hiw, low);
                *reinterpret_cast<uint32_t*>(&AH[r * 136 + col]) = hiw;
                *reinterpret_cast<uint32_t*>(&AL[r * 136 + col]) = low;
            }
        }
    }
    __syncthreads();
    issue_chunk(69632, 87040, (const char*)g_wqkvh + 64 * 256,
                              (const char*)g_wqkvl + 64 * 256);

    uint32_t* gqh = reinterpret_cast<uint32_t*>(g_qhi);
    uint32_t* gql = reinterpret_cast<uint32_t*>(g_qlo);
    uint32_t* gkh = reinterpret_cast<uint32_t*>(g_khi);
    uint32_t* gkl = reinterpret_cast<uint32_t*>(g_klo);

    // chunk2: q cols 0..63 (B0)
    {
        float acc[4][4];
        #pragma unroll
        for (int j = 0; j < 4; j++)
            #pragma unroll
            for (int t = 0; t < 4; t++) acc[j][t] = 0.f;
        CP_WAIT1();
        __syncthreads();
        gemm_chunk(AHw, ALw, B0H, B0L, wbase, g, qq, nh, acc);
        #pragma unroll
        for (int j = 0; j < 4; ++j) {
            const int h = nh * 32 + j * 8 + q2;
            #pragma unroll
            for (int hf = 0; hf < 2; ++hf) {
                const int r = wbase + g + hf * 8;
                uint32_t hiw, low;
                split_pack(acc[j][hf * 2] * SCALE, acc[j][hf * 2 + 1] * SCALE,
                           hiw, low);
                size_t widx = (size_t)(tok0 + r) * 32 + (h >> 1);
                gqh[widx] = hiw; gql[widx] = low;
            }
        }
        __syncthreads();
    }
    issue_chunk(34816, 52224, (const char*)g_wqkvh + 128 * 256,
                              (const char*)g_wqkvl + 128 * 256);

    // chunk3: k cols 0..63 (B1)
    {
        float acc[4][4];
        #pragma unroll
        for (int j = 0; j < 4; j++)
            #pragma unroll
            for (int t = 0; t < 4; t++) acc[j][t] = 0.f;
        CP_WAIT1();
        __syncthreads();
        gemm_chunk(AHw, ALw, B1H, B1L, wbase, g, qq, nh, acc);
        #pragma unroll
        for (int j = 0; j < 4; ++j) {
            const int h = nh * 32 + j * 8 + q2;
            #pragma unroll
            for (int hf = 0; hf < 2; ++hf) {
                const int r = wbase + g + hf * 8;
                uint32_t hiw, low;
                split_pack(acc[j][hf * 2], acc[j][hf * 2 + 1], hiw, low);
                size_t widx = (size_t)(tok0 + r) * 32 + (h >> 1);
                gkh[widx] = hiw; gkl[widx] = low;
            }
        }
    }

    // chunk4: v cols 0..63 (B0)
    {
        float acc[4][4];
        #pragma unroll
        for (int j = 0; j < 4; j++)
            #pragma unroll
            for (int t = 0; t < 4; t++) acc[j][t] = 0.f;
        CP_WAIT0();
        __syncthreads();
        gemm_chunk(AHw, ALw, B0H, B0L, wbase, g, qq, nh, acc);
        __syncthreads();
        #pragma unroll
        for (int j = 0; j < 4; ++j) {
            const int h = nh * 32 + j * 8 + q2;
            const int r = wbase + g;
            vT[h * 68 + r]           = acc[j][0];
            vT[(h + 1) * 68 + r]     = acc[j][1];
            vT[h * 68 + r + 8]       = acc[j][2];
            vT[(h + 1) * 68 + r + 8] = acc[j][3];
        }
    }
    __syncthreads();

    uint32_t* gvh = reinterpret_cast<uint32_t*>(g_vhi);
    uint32_t* gvl = reinterpret_cast<uint32_t*>(g_vlo);
    for (int i = tid; i < 64 * 32; i += 256) {
        int h = i >> 5, tw = i & 31;
        int t = tw * 2;
        uint32_t hiw, low;
        split_pack(vT[h * 68 + t], vT[h * 68 + t + 1], hiw, low);
        size_t widx = ((size_t)bb * 64 + h) * 256 + ((t0 + t) >> 1);
        gvh[widx] = hiw; gvl[widx] = low;
    }
}

// ---------------------------------------------------------------------------
// Kernel 2: causal flash attention, 64-q-row CTAs, 2 CTAs/SM, DOUBLE-BUFFERED
// 64-key tiles. grid (8 qtiles, 128 b), 256 threads = 4 q-groups x 2 key-halves
// (each warp 16 rows x 32 keys per tile).
// smem words: QH 2304 @0, QL @2304; buf b at 4608 + b*9216:
//   KH 2304 (64x36), KL 2304, VH 2304 (64x36), VL 2304.
// total 23040 words = 92160 B -> 2 CTAs/SM.
// ---------------------------------------------------------------------------
#define K2_SMEM 92160

__global__ __launch_bounds__(256, 2)
void head_k2_attn(float* __restrict__ out)
{
    extern __shared__ char smc[];
    const uint32_t sbase = smem_u32(smc);
    uint32_t* S = reinterpret_cast<uint32_t*>(smc);
    const uint32_t* QHw = S;
    const uint32_t* QLw = S + 2304;

    const int tid   = threadIdx.x;
    const int wid   = tid >> 5;
    const int lane  = tid & 31;
    const int g     = lane >> 2;
    const int qq    = lane & 3;
    const int q2    = qq * 2;
    const int qg    = wid & 3;          // q group 0..3 (16 rows each)
    const int kh    = wid >> 2;         // key half within a 64-key tile
    const int wbase = qg * 16;
    const int qt    = blockIdx.x;       // 0..7 (64-row q tiles)
    const int b     = blockIdx.y;
    const int q0    = qt * 64;
    const int nt    = qt + 1;           // number of 64-key tiles

    const uint32_t* gqh = reinterpret_cast<const uint32_t*>(g_qhi);
    const uint32_t* gql = reinterpret_cast<const uint32_t*>(g_qlo);
    const uint32_t* gkh = reinterpret_cast<const uint32_t*>(g_khi);
    const uint32_t* gkl = reinterpret_cast<const uint32_t*>(g_klo);
    const uint32_t* gvh = reinterpret_cast<const uint32_t*>(g_vhi);
    const uint32_t* gvl = reinterpret_cast<const uint32_t*>(g_vlo);

    // issue K/V tile jt into buffer bsel
    auto issue_tile = [&](int jt, int bsel) {
        const uint32_t bufw = 4608u + (uint32_t)bsel * 9216u;
        size_t kbase = ((size_t)b * 512 + jt * 64) * 32;
        for (int i = tid; i < 512; i += 256) {
            int row = i >> 3, cw = (i & 7) * 4;
            uint32_t dof = (bufw + (uint32_t)(row * 36 + cw)) * 4;
            cp_async16(sbase + dof,            gkh + kbase + row * 32 + cw);
            cp_async16(sbase + dof + 2304 * 4, gkl + kbase + row * 32 + cw);
        }
        size_t vbase = (size_t)b * 64 * 256 + jt * 32;
        for (int i = tid; i < 512; i += 256) {
            int h = i >> 3, cw = (i & 7) * 4;
            uint32_t dof = (bufw + 4608u + (uint32_t)(h * 36 + cw)) * 4;
            cp_async16(sbase + dof,            gvh + vbase + h * 256 + cw);
            cp_async16(sbase + dof + 2304 * 4, gvl + vbase + h * 256 + cw);
        }
        CP_COMMIT();
    };

    // ---- group0: Q + tile0 ----
    {
        size_t qbase = ((size_t)b * 512 + q0) * 32;
        for (int i = tid; i < 512; i += 256) {
            int row = i >> 3, cw = (i & 7) * 4;
            uint32_t dof = (uint32_t)(row * 36 + cw) * 4;
            cp_async16(sbase + dof,            gqh + qbase + row * 32 + cw);
            cp_async16(sbase + 2304 * 4 + dof, gql + qbase + row * 32 + cw);
        }
        size_t kbase = (size_t)b * 512 * 32;
        for (int i = tid; i < 512; i += 256) {
            int row = i >> 3, cw = (i & 7) * 4;
            uint32_t dof = (4608u + (uint32_t)(row * 36 + cw)) * 4;
            cp_async16(sbase + dof,            gkh + kbase + row * 32 + cw);
            cp_async16(sbase + dof + 2304 * 4, gkl + kbase + row * 32 + cw);
        }
        size_t vbase = (size_t)b * 64 * 256;
        for (int i = tid; i < 512; i += 256) {
            int h = i >> 3, cw = (i & 7) * 4;
            uint32_t dof = (4608u + 4608u + (uint32_t)(h * 36 + cw)) * 4;
            cp_async16(sbase + dof,            gvh + vbase + h * 256 + cw);
            cp_async16(sbase + dof + 2304 * 4, gvl + vbase + h * 256 + cw);
        }
        CP_COMMIT();
    }

    float o[8][4];
    #pragma unroll
    for (int j = 0; j < 8; j++)
        #pragma unroll
        for (int t = 0; t < 4; t++) o[j][t] = 0.f;
    float m0 = -1e30f, m1 = -1e30f, l0 = 0.f, l1 = 0.f;

    for (int jt = 0; jt < nt; ++jt) {
        if (jt) __syncthreads();            // frees buf[(jt+1)&1]
        if (jt + 1 < nt) issue_tile(jt + 1, (jt + 1) & 1);
        if (jt + 1 < nt) { CP_WAIT1(); } else { CP_WAIT0(); }
        __syncthreads();

        // skip warp-tiles whose keys all exceed this warp's max row
        if (jt * 64 + kh * 32 > q0 + wbase + 15) continue;

        const uint32_t* KHw = S + 4608 + (jt & 1) * 9216;
        const uint32_t* KLw = KHw + 2304;
        const uint32_t* VHw = KHw + 4608;
        const uint32_t* VLw = KHw + 6912;

        // ---- S = Q K^T (16 rows x 32 keys per warp) ----
        float s[4][4];
        #pragma unroll
        for (int j = 0; j < 4; j++)
            #pragma unroll
            for (int t = 0; t < 4; t++) s[j][t] = 0.f;

        #pragma unroll
        for (int kk = 0; kk < 4; ++kk) {
            const int kw = kk * 8 + qq;
            const int r0w = wbase + g;
            uint32_t qh[4], ql[4];
            qh[0] = QHw[r0w * 36 + kw];     qh[1] = QHw[(r0w + 8) * 36 + kw];
            qh[2] = QHw[r0w * 36 + kw + 4]; qh[3] = QHw[(r0w + 8) * 36 + kw + 4];
            ql[0] = QLw[r0w * 36 + kw];     ql[1] = QLw[(r0w + 8) * 36 + kw];
            ql[2] = QLw[r0w * 36 + kw + 4]; ql[3] = QLw[(r0w + 8) * 36 + kw + 4];
            #pragma unroll
            for (int j = 0; j < 4; ++j) {
                const int n = kh * 32 + j * 8 + g;
                uint32_t bh[2] = { KHw[n * 36 + kw], KHw[n * 36 + kw + 4] };
                uint32_t bl[2] = { KLw[n * 36 + kw], KLw[n * 36 + kw + 4] };
                mma_bf16(s[j], qh, bh);
                mma_bf16(s[j], qh, bl);
                mma_bf16(s[j], ql, bh);
            }
        }

        // ---- causal mask (only the last tile straddles the diagonal) ----
        if (jt == nt - 1) {
            const int r0 = q0 + wbase + g;
            const int cb = jt * 64 + kh * 32;
            #pragma unroll
            for (int j = 0; j < 4; ++j) {
                const int c0 = cb + j * 8 + q2;
                if (c0     > r0)     s[j][0] = -1e30f;
                if (c0 + 1 > r0)     s[j][1] = -1e30f;
                if (c0     > r0 + 8) s[j][2] = -1e30f;
                if (c0 + 1 > r0 + 8) s[j][3] = -1e30f;
            }
        }

        // ---- online softmax (quad shuffles per row) ----
        float mx0 = -1e30f, mx1 = -1e30f;
        #pragma unroll
        for (int j = 0; j < 4; ++j) {
            mx0 = fmaxf(mx0, fmaxf(s[j][0], s[j][1]));
            mx1 = fmaxf(mx1, fmaxf(s[j][2], s[j][3]));
        }
        mx0 = fmaxf(mx0, __shfl_xor_sync(0xffffffffu, mx0, 1));
        mx0 = fmaxf(mx0, __shfl_xor_sync(0xffffffffu, mx0, 2));
        mx1 = fmaxf(mx1, __shfl_xor_sync(0xffffffffu, mx1, 1));
        mx1 = fmaxf(mx1, __shfl_xor_sync(0xffffffffu, mx1, 2));
        const float mn0 = fmaxf(m0, mx0), mn1 = fmaxf(m1, mx1);
        const float a0 = __expf(m0 - mn0), a1 = __expf(m1 - mn1);
        m0 = mn0; m1 = mn1;
        l0 *= a0; l1 *= a1;
        #pragma unroll
        for (int j = 0; j < 8; ++j) {
            o[j][0] *= a0; o[j][1] *= a0; o[j][2] *= a1; o[j][3] *= a1;
        }
        float s0 = 0.f, s1 = 0.f;
        #pragma unroll
        for (int j = 0; j < 4; ++j) {
            s[j][0] = __expf(s[j][0] - mn0); s0 += s[j][0];
            s[j][1] = __expf(s[j][1] - mn0); s0 += s[j][1];
            s[j][2] = __expf(s[j][2] - mn1); s1 += s[j][2];
            s[j][3] = __expf(s[j][3] - mn1); s1 += s[j][3];
        }
        s0 += __shfl_xor_sync(0xffffffffu, s0, 1);
        s0 += __shfl_xor_sync(0xffffffffu, s0, 2);
        s1 += __shfl_xor_sync(0xffffffffu, s1, 1);
        s1 += __shfl_xor_sync(0xffffffffu, s1, 2);
        l0 += s0; l1 += s1;

        // ---- O += P @ V over this warp's 32 keys ----
        #pragma unroll
        for (int kk2 = 0; kk2 < 2; ++kk2) {
            const int j0 = kk2 * 2, j1 = j0 + 1;
            uint32_t ah[4], al[4];
            ah[0] = pack_bf16(s[j0][0], s[j0][1]);
            ah[1] = pack_bf16(s[j0][2], s[j0][3]);
            ah[2] = pack_bf16(s[j1][0], s[j1][1]);
            ah[3] = pack_bf16(s[j1][2], s[j1][3]);
            al[0] = pack_bf16(bf16_residual(s[j0][0]), bf16_residual(s[j0][1]));
            al[1] = pack_bf16(bf16_residual(s[j0][2]), bf16_residual(s[j0][3]));
            al[2] = pack_bf16(bf16_residual(s[j1][0]), bf16_residual(s[j1][1]));
            al[3] = pack_bf16(bf16_residual(s[j1][2]), bf16_residual(s[j1][3]));
            const int kwv = kh * 16 + kk2 * 8 + qq;
            #pragma unroll
            for (int jn = 0; jn < 8; ++jn) {
                const int hN = jn * 8 + g;
                uint32_t vh[2] = { VHw[hN * 36 + kwv], VHw[hN * 36 + kwv + 4] };
                uint32_t vl[2] = { VLw[hN * 36 + kwv], VLw[hN * 36 + kwv + 4] };
                mma_bf16(o[jn], ah, vh);
                mma_bf16(o[jn], ah, vl);
                mma_bf16(o[jn], al, vh);
            }
        }
    }

    // ---- merge key-halves through smem (overlay buf0 region), write out ----
    __syncthreads();                          // everyone done with K/V buffers
    float* oB = reinterpret_cast<float*>(S + 4608);   // 64 x 68 floats
    float* mB = reinterpret_cast<float*>(S + 9216);   // 64
    float* lB = mB + 64;

    if (kh == 1) {
        #pragma unroll
        for (int j = 0; j < 8; ++j) {
            const int h = j * 8 + q2;
            oB[(wbase + g) * 68 + h]         = o[j][0];
            oB[(wbase + g) * 68 + h + 1]     = o[j][1];
            oB[(wbase + 8 + g) * 68 + h]     = o[j][2];
            oB[(wbase + 8 + g) * 68 + h + 1] = o[j][3];
        }
        if (qq == 0) {
            mB[wbase + g] = m0;     lB[wbase + g] = l0;
            mB[wbase + 8 + g] = m1; lB[wbase + 8 + g] = l1;
        }
    }
    __syncthreads();

    if (kh == 0) {
        const int r0 = wbase + g, r1 = r0 + 8;
        const float mb0 = mB[r0], mb1 = mB[r1];
        const float mF0 = fmaxf(m0, mb0), mF1 = fmaxf(m1, mb1);
        const float aA0 = __expf(m0 - mF0), aB0 = __expf(mb0 - mF0);
        const float aA1 = __expf(m1 - mF1), aB1 = __expf(mb1 - mF1);
        const float i0 = 1.f / (l0 * aA0 + lB[r0] * aB0);
        const float i1 = 1.f / (l1 * aA1 + lB[r1] * aB1);
        const int gr0 = q0 + r0;
        const size_t ob = (size_t)b * TSEQ * HDIM;
        #pragma unroll
        for (int jn = 0; jn < 8; ++jn) {
            const int h = jn * 8 + q2;
            float2 v0, v1;
            v0.x = (o[jn][0] * aA0 + oB[r0 * 68 + h]     * aB0) * i0;
            v0.y = (o[jn][1] * aA0 + oB[r0 * 68 + h + 1] * aB0) * i0;
            v1.x = (o[jn][2] * aA1 + oB[r1 * 68 + h]     * aB1) * i1;
            v1.y = (o[jn][3] * aA1 + oB[r1 * 68 + h + 1] * aB1) * i1;
            *reinterpret_cast<float2*>(out + ob + (size_t)gr0 * 64 + h)       = v0;
            *reinterpret_cast<float2*>(out + ob + (size_t)(gr0 + 8) * 64 + h) = v1;
        }
    }
}

// ---------------------------------------------------------------------------
extern "C" void kernel_launch(void* const* d_in, const int* in_sizes, int n_in,
                              void* d_out, int out_size)
{
    const float* x  = (const float*)d_in[0];
    const float* Wg = (const float*)d_in[1];
    const float* bg = (const float*)d_in[2];
    const float* Wk = (const float*)d_in[3];
    const float* Wq = (const float*)d_in[4];
    const float* Wv = (const float*)d_in[5];
    float* out = (float*)d_out;

    cudaFuncSetAttribute(head_k1_gate_qkv,
                         cudaFuncAttributeMaxDynamicSharedMemorySize, K1_SMEM);
    cudaFuncSetAttribute(head_k2_attn,
                         cudaFuncAttributeMaxDynamicSharedMemorySize, K2_SMEM);

    head_k0_split<<<160, 256>>>(Wg, Wk, Wq, Wv);
    head_k1_gate_qkv<<<BT / 64, 256, K1_SMEM>>>(x, bg);
    head_k2_attn<<<dim3(8, 128), 256, K2_SMEM>>>(out);
}